// round 3
// baseline (speedup 1.0000x reference)
#include <cuda_runtime.h>
#include <math.h>

#define N_NODES  50000
#define N_EDGES  800000
#define N_GRAPHS 512
#define IN_DIM   128
#define HID      256
#define OUT_DIM  40

// ---------------- scratch (device globals; no allocation allowed) ----------------
__device__ float g_agg[(size_t)N_NODES * HID];
__device__ float g_tmp[(size_t)N_NODES * HID];
__device__ float g_hA [(size_t)N_NODES * HID];
__device__ float g_hB [(size_t)N_NODES * HID];
__device__ int   g_deg[N_NODES];
__device__ int   g_rowptr[N_NODES + 1];
__device__ int   g_cursor[N_NODES];
__device__ int   g_eidx[N_EDGES];
__device__ float g_pool[N_GRAPHS * HID];

// ---------------- CSR build ----------------
__global__ void hist_k(const int* __restrict__ dst) {
    int e = blockIdx.x * blockDim.x + threadIdx.x;
    if (e < N_EDGES) atomicAdd(&g_deg[dst[e]], 1);
}

// single-block exclusive scan of g_deg -> g_rowptr (50001 entries)
__global__ void scan_k() {
    __shared__ int buf[1024];
    __shared__ int carry;
    int tid = threadIdx.x;
    if (tid == 0) carry = 0;
    __syncthreads();
    for (int base = 0; base < N_NODES; base += 1024) {
        int v = (base + tid < N_NODES) ? g_deg[base + tid] : 0;
        buf[tid] = v;
        __syncthreads();
        for (int off = 1; off < 1024; off <<= 1) {
            int t = (tid >= off) ? buf[tid - off] : 0;
            __syncthreads();
            buf[tid] += t;
            __syncthreads();
        }
        int c0 = carry;
        if (base + tid < N_NODES) g_rowptr[base + tid] = buf[tid] - v + c0;
        __syncthreads();
        if (tid == 0) carry += buf[1023];
        __syncthreads();
    }
    if (tid == 0) g_rowptr[N_NODES] = carry;
}

__global__ void fill_k(const int* __restrict__ src, const int* __restrict__ dst) {
    int e = blockIdx.x * blockDim.x + threadIdx.x;
    if (e < N_EDGES) {
        int d = dst[e];
        int p = atomicAdd(&g_cursor[d], 1);
        g_eidx[p] = src[e];
    }
}

// ---------------- neighbor aggregation (gather via CSR) ----------------
// thread = (node, float4 chunk). D4 = D/4. Warp covers chunks of ONE node
// (D4 is 32 or 64) -> no divergence, eidx load is a warp broadcast.
__global__ void agg_k(const float* __restrict__ X, float* __restrict__ AGG, int D4) {
    int gid  = blockIdx.x * blockDim.x + threadIdx.x;
    int node = gid / D4;
    int c    = gid - node * D4;
    int s = g_rowptr[node];
    int e = g_rowptr[node + 1];
    const float4* x4 = (const float4*)X;
    float4 acc = make_float4(0.f, 0.f, 0.f, 0.f);
    for (int j = s; j < e; j++) {
        int sidx = g_eidx[j];
        float4 v = __ldg(&x4[(size_t)sidx * D4 + c]);
        acc.x += v.x; acc.y += v.y; acc.z += v.z; acc.w += v.w;
    }
    ((float4*)AGG)[(size_t)node * D4 + c] = acc;
}

// ---------------- fused SGEMM ----------------
// C[N,M] = epilogue( A' @ B + bias ), A' = FUSE_ADD ? (1+eps)*A + A2 : A
// epilogue: relu, then optional BN (eval mode): v*gamma/sqrt(1+1e-5) + beta
template<bool FUSE_ADD, bool BN_OUT>
__global__ void __launch_bounds__(256, 2) gemm_k(
    const float* __restrict__ A, const float* __restrict__ A2,
    const float* __restrict__ epsp,
    const float* __restrict__ B, const float* __restrict__ bias,
    const float* __restrict__ gamma, const float* __restrict__ beta,
    float* __restrict__ C, int N, int K, int M)
{
    const int BM = 128, BN = 128, BK = 16, TM = 8, TN = 8;
    __shared__ float As[BK][BM];
    __shared__ float Bs[BK][BN];
    int tid = threadIdx.x;
    int tx = tid & 15, ty = tid >> 4;
    int rowBase = blockIdx.y * BM;
    int colBase = blockIdx.x * BN;

    float alpha = 1.0f;
    if (FUSE_ADD) alpha = 1.0f + __ldg(epsp);

    float acc[TM][TN];
    #pragma unroll
    for (int i = 0; i < TM; i++)
        #pragma unroll
        for (int j = 0; j < TN; j++) acc[i][j] = 0.f;

    int a_r = tid >> 2;          // 0..63
    int a_c = (tid & 3) << 2;    // 0,4,8,12
    int b_r = tid >> 5;          // 0..7
    int b_c = (tid & 31) << 2;   // 0..124

    for (int k0 = 0; k0 < K; k0 += BK) {
        #pragma unroll
        for (int i = 0; i < 2; i++) {
            int r = a_r + i * 64;
            int grow = rowBase + r;
            float4 v = make_float4(0.f, 0.f, 0.f, 0.f);
            if (grow < N) {
                v = *(const float4*)(A + (size_t)grow * K + k0 + a_c);
                if (FUSE_ADD) {
                    float4 w = *(const float4*)(A2 + (size_t)grow * K + k0 + a_c);
                    v.x = alpha * v.x + w.x; v.y = alpha * v.y + w.y;
                    v.z = alpha * v.z + w.z; v.w = alpha * v.w + w.w;
                }
            }
            As[a_c + 0][r] = v.x; As[a_c + 1][r] = v.y;
            As[a_c + 2][r] = v.z; As[a_c + 3][r] = v.w;
        }
        #pragma unroll
        for (int i = 0; i < 2; i++) {
            int r = b_r + i * 8;
            *(float4*)&Bs[r][b_c] =
                *(const float4*)(B + (size_t)(k0 + r) * M + colBase + b_c);
        }
        __syncthreads();

        #pragma unroll
        for (int kk = 0; kk < BK; kk++) {
            float ar[TM], br[TN];
            *(float4*)&ar[0] = *(const float4*)&As[kk][ty * TM];
            *(float4*)&ar[4] = *(const float4*)&As[kk][ty * TM + 4];
            *(float4*)&br[0] = *(const float4*)&Bs[kk][tx * TN];
            *(float4*)&br[4] = *(const float4*)&Bs[kk][tx * TN + 4];
            #pragma unroll
            for (int i = 0; i < TM; i++)
                #pragma unroll
                for (int j = 0; j < TN; j++)
                    acc[i][j] = fmaf(ar[i], br[j], acc[i][j]);
        }
        __syncthreads();
    }

    const float bnmul = rsqrtf(1.0f + 1e-5f);
    #pragma unroll
    for (int i = 0; i < TM; i++) {
        int row = rowBase + ty * TM + i;
        if (row < N) {
            #pragma unroll
            for (int j = 0; j < TN; j++) {
                int col = colBase + tx * TN + j;
                float v = acc[i][j] + __ldg(&bias[col]);
                v = fmaxf(v, 0.f);
                if (BN_OUT)
                    v = v * (__ldg(&gamma[col]) * bnmul) + __ldg(&beta[col]);
                C[(size_t)row * M + col] = v;
            }
        }
    }
}

// ---------------- pooling (batch is sorted -> binary search ranges) ----------------
__device__ __forceinline__ int lbound(const int* a, int n, int v) {
    int lo = 0, hi = n;
    while (lo < hi) { int m = (lo + hi) >> 1; if (a[m] < v) lo = m + 1; else hi = m; }
    return lo;
}

__global__ void pool_k(const float* __restrict__ H, const int* __restrict__ batch) {
    int g = blockIdx.x;
    int t = threadIdx.x;
    __shared__ int ss, se;
    if (t == 0)  ss = lbound(batch, N_NODES, g);
    if (t == 32) se = lbound(batch, N_NODES, g + 1);
    __syncthreads();
    int start = ss, end = se;
    int c = t & 63, sub = t >> 6;     // 64 chunks x 4 node-strides
    const float4* h4 = (const float4*)H;
    float4 acc = make_float4(0.f, 0.f, 0.f, 0.f);
    for (int i = start + sub; i < end; i += 4) {
        float4 v = h4[(size_t)i * 64 + c];
        acc.x += v.x; acc.y += v.y; acc.z += v.z; acc.w += v.w;
    }
    __shared__ float4 red[256];
    red[t] = acc;
    __syncthreads();
    if (sub == 0) {
        float4 a = red[c], b = red[c + 64], c2 = red[c + 128], d = red[c + 192];
        int cnt = end - start;
        float inv = 1.0f / (float)(cnt > 1 ? cnt : 1);
        float4 o;
        o.x = (a.x + b.x + c2.x + d.x) * inv;
        o.y = (a.y + b.y + c2.y + d.y) * inv;
        o.z = (a.z + b.z + c2.z + d.z) * inv;
        o.w = (a.w + b.w + c2.w + d.w) * inv;
        ((float4*)g_pool)[g * 64 + c] = o;
    }
}

// ---------------- final MLP + log_softmax (one block per graph) ----------------
__global__ void final_k(const float* __restrict__ lw1, const float* __restrict__ lb1,
                        const float* __restrict__ lw2, const float* __restrict__ lb2,
                        float* __restrict__ out)
{
    int g = blockIdx.x, t = threadIdx.x;
    __shared__ float p[HID], o1[HID], o2[OUT_DIM];
    __shared__ float s_m, s_l;
    p[t] = g_pool[g * HID + t];
    __syncthreads();
    float acc = __ldg(&lb1[t]);
    for (int k = 0; k < HID; k++) acc = fmaf(p[k], __ldg(&lw1[k * HID + t]), acc);
    o1[t] = fmaxf(acc, 0.f);
    __syncthreads();
    if (t < OUT_DIM) {
        float a = __ldg(&lb2[t]);
        for (int k = 0; k < HID; k++) a = fmaf(o1[k], __ldg(&lw2[k * OUT_DIM + t]), a);
        o2[t] = a;
    }
    __syncthreads();
    if (t == 0) {
        float m = -1e30f;
        for (int j = 0; j < OUT_DIM; j++) m = fmaxf(m, o2[j]);
        float s = 0.f;
        for (int j = 0; j < OUT_DIM; j++) s += expf(o2[j] - m);
        s_m = m; s_l = logf(s);
    }
    __syncthreads();
    if (t < OUT_DIM) out[g * OUT_DIM + t] = o2[t] - s_m - s_l;
}

// ---------------- launcher ----------------
extern "C" void kernel_launch(void* const* d_in, const int* in_sizes, int n_in,
                              void* d_out, int out_size)
{
    const float* x    = (const float*)d_in[0];
    const int*   ei   = (const int*)  d_in[1];
    const int*   batch= (const int*)  d_in[2];
    const float* w1a  = (const float*)d_in[3];
    const float* b1a  = (const float*)d_in[4];
    const float* w2a  = (const float*)d_in[5];
    const float* b2a  = (const float*)d_in[6];
    const float* ga   = (const float*)d_in[7];
    const float* bba  = (const float*)d_in[8];
    const float* eps0 = (const float*)d_in[9];
    const float* w1r  = (const float*)d_in[10];
    const float* b1r  = (const float*)d_in[11];
    const float* w2r  = (const float*)d_in[12];
    const float* b2r  = (const float*)d_in[13];
    const float* gr   = (const float*)d_in[14];
    const float* br   = (const float*)d_in[15];
    const float* epsr = (const float*)d_in[16];
    const float* lw1  = (const float*)d_in[17];
    const float* lb1  = (const float*)d_in[18];
    const float* lw2  = (const float*)d_in[19];
    const float* lb2  = (const float*)d_in[20];
    float* out = (float*)d_out;

    const int* src = ei;
    const int* dst = ei + N_EDGES;

    void *agg_p, *tmp_p, *hA_p, *hB_p, *deg_p, *rp_p, *cur_p;
    cudaGetSymbolAddress(&agg_p, g_agg);
    cudaGetSymbolAddress(&tmp_p, g_tmp);
    cudaGetSymbolAddress(&hA_p,  g_hA);
    cudaGetSymbolAddress(&hB_p,  g_hB);
    cudaGetSymbolAddress(&deg_p, g_deg);
    cudaGetSymbolAddress(&rp_p,  g_rowptr);
    cudaGetSymbolAddress(&cur_p, g_cursor);

    float* agg = (float*)agg_p;
    float* tmp = (float*)tmp_p;
    float* hA  = (float*)hA_p;
    float* hB  = (float*)hB_p;

    // --- CSR build (once per call, reused by all 4 layers) ---
    cudaMemsetAsync(deg_p, 0, N_NODES * sizeof(int));
    hist_k<<<(N_EDGES + 255) / 256, 256>>>(dst);
    scan_k<<<1, 1024>>>();
    cudaMemcpyAsync(cur_p, rp_p, N_NODES * sizeof(int), cudaMemcpyDeviceToDevice);
    fill_k<<<(N_EDGES + 255) / 256, 256>>>(src, dst);

    dim3 grid(HID / 128, (N_NODES + 127) / 128);

    // --- layer 1 (IN_DIM -> HID) ---
    agg_k<<<(N_NODES * (IN_DIM / 4)) / 256, 256>>>(x, agg, IN_DIM / 4);
    gemm_k<true,  false><<<grid, 256>>>(x,   agg, eps0, w1a, b1a, nullptr, nullptr,
                                        tmp, N_NODES, IN_DIM, HID);
    gemm_k<false, true ><<<grid, 256>>>(tmp, nullptr, nullptr, w2a, b2a, ga, bba,
                                        hA,  N_NODES, HID, HID);

    // --- layers 2..4 (HID -> HID) ---
    const float* hin = hA;
    float* hout = hB;
    for (int i = 0; i < 3; i++) {
        agg_k<<<(N_NODES * (HID / 4)) / 256, 256>>>(hin, agg, HID / 4);
        gemm_k<true,  false><<<grid, 256>>>(hin, agg, epsr + i,
                                            w1r + (size_t)i * HID * HID, b1r + i * HID,
                                            nullptr, nullptr, tmp, N_NODES, HID, HID);
        gemm_k<false, true ><<<grid, 256>>>(tmp, nullptr, nullptr,
                                            w2r + (size_t)i * HID * HID, b2r + i * HID,
                                            gr + i * HID, br + i * HID,
                                            hout, N_NODES, HID, HID);
        const float* t2 = hin; hin = hout; hout = (float*)t2;
    }

    // --- pooling + head ---
    pool_k<<<N_GRAPHS, 256>>>(hin, batch);
    final_k<<<N_GRAPHS, 256>>>(lw1, lb1, lw2, lb2, out);
}